// round 2
// baseline (speedup 1.0000x reference)
#include <cuda_runtime.h>
#include <cstdint>

// Edge-wise u·v scoring (DGL fn.u_dot_v)
//   d_in[0] user_h : [100000, 128] float32
//   d_in[1] game_h : [ 50000, 128] float32
//   d_in[2] src_idx: [E] int32  (harness downcasts the reference's int64)
//   d_in[3] dst_idx: [E] int32
//   d_out   score  : [E, 1] float32
//
// One warp per edge: lane k loads float4 #k of each 128-float row
// (perfectly coalesced, 4 x 128B lines per row), 4 FMAs, butterfly
// shuffle reduce, lane 0 writes. Tables total 77 MB -> mostly L2-resident;
// kernel should be L2-bandwidth-bound.

#define WARPS_PER_BLOCK 8
#define THREADS_PER_BLOCK (WARPS_PER_BLOCK * 32)

__global__ void __launch_bounds__(THREADS_PER_BLOCK)
edge_dot_kernel(const float* __restrict__ user_h,
                const float* __restrict__ game_h,
                const int* __restrict__ src_idx,
                const int* __restrict__ dst_idx,
                float* __restrict__ out,
                int num_edges,
                int n_users,
                int n_games)
{
    const int warp_in_block = threadIdx.x >> 5;
    const int lane          = threadIdx.x & 31;
    const int e = blockIdx.x * WARPS_PER_BLOCK + warp_in_block;
    if (e >= num_edges) return;

    // Per-warp uniform index loads; clamp defensively so a layout/dtype
    // surprise shows up as rel_err, not an illegal access.
    int su = src_idx[e];
    int sg = dst_idx[e];
    su = min(max(su, 0), n_users - 1);
    sg = min(max(sg, 0), n_games - 1);

    const float4* __restrict__ urow =
        reinterpret_cast<const float4*>(user_h + (size_t)su * 128);
    const float4* __restrict__ grow =
        reinterpret_cast<const float4*>(game_h + (size_t)sg * 128);

    const float4 u = __ldg(&urow[lane]);
    const float4 v = __ldg(&grow[lane]);

    float acc = u.x * v.x;
    acc = fmaf(u.y, v.y, acc);
    acc = fmaf(u.z, v.z, acc);
    acc = fmaf(u.w, v.w, acc);

    #pragma unroll
    for (int ofs = 16; ofs > 0; ofs >>= 1)
        acc += __shfl_xor_sync(0xFFFFFFFFu, acc, ofs);

    if (lane == 0)
        out[e] = acc;
}

extern "C" void kernel_launch(void* const* d_in, const int* in_sizes, int n_in,
                              void* d_out, int out_size)
{
    const float* user_h  = (const float*)d_in[0];
    const float* game_h  = (const float*)d_in[1];
    const int*   src_idx = (const int*)d_in[2];
    const int*   dst_idx = (const int*)d_in[3];
    float*       out     = (float*)d_out;

    const int num_edges = in_sizes[2];          // E
    const int n_users   = in_sizes[0] / 128;    // rows of user_h
    const int n_games   = in_sizes[1] / 128;    // rows of game_h

    const int grid = (num_edges + WARPS_PER_BLOCK - 1) / WARPS_PER_BLOCK;
    edge_dot_kernel<<<grid, THREADS_PER_BLOCK>>>(
        user_h, game_h, src_idx, dst_idx, out, num_edges, n_users, n_games);
}

// round 3
// speedup vs baseline: 1.9553x; 1.9553x over previous
#include <cuda_runtime.h>
#include <cstdint>

// Edge-wise u·v scoring (DGL fn.u_dot_v)
//   d_in[0] user_h : [100000, 128] float32
//   d_in[1] game_h : [ 50000, 128] float32
//   d_in[2] src_idx: [E] int32
//   d_in[3] dst_idx: [E] int32
//   d_out   score  : [E, 1] float32
//
// R3: warp processes 4 edges; all 8 gather LDG.128s issued up front
// (per-lane MLP 2 -> 8) to cover L2/DRAM latency that R2's ncu showed
// exposed (issue 37%, no pipe saturated). Feature loads bypass L1 (.cg)
// since gather L1 hit rate is ~0.

#define WARPS_PER_BLOCK 8
#define THREADS_PER_BLOCK (WARPS_PER_BLOCK * 32)
#define EDGES_PER_WARP 4

__device__ __forceinline__ float4 ldcg_f4(const float4* p) {
    return __ldcg(p);
}

__device__ __forceinline__ float warp_reduce(float acc) {
    #pragma unroll
    for (int ofs = 16; ofs > 0; ofs >>= 1)
        acc += __shfl_xor_sync(0xFFFFFFFFu, acc, ofs);
    return acc;
}

__global__ void __launch_bounds__(THREADS_PER_BLOCK)
edge_dot_kernel(const float* __restrict__ user_h,
                const float* __restrict__ game_h,
                const int* __restrict__ src_idx,
                const int* __restrict__ dst_idx,
                float* __restrict__ out,
                int num_edges,
                int n_users,
                int n_games)
{
    const int warp_in_block = threadIdx.x >> 5;
    const int lane          = threadIdx.x & 31;
    const int warp_id = blockIdx.x * WARPS_PER_BLOCK + warp_in_block;
    const int e0 = warp_id * EDGES_PER_WARP;
    if (e0 >= num_edges) return;

    if (e0 + EDGES_PER_WARP <= num_edges) {
        // ---- fast path: full batch of 4 edges ----
        int su[EDGES_PER_WARP], sg[EDGES_PER_WARP];
        #pragma unroll
        for (int i = 0; i < EDGES_PER_WARP; i++) {
            su[i] = min(max(src_idx[e0 + i], 0), n_users - 1);
            sg[i] = min(max(dst_idx[e0 + i], 0), n_games - 1);
        }

        // Issue all 8 gather loads before consuming any (max MLP).
        float4 u[EDGES_PER_WARP], v[EDGES_PER_WARP];
        #pragma unroll
        for (int i = 0; i < EDGES_PER_WARP; i++) {
            u[i] = ldcg_f4(reinterpret_cast<const float4*>(
                       user_h + (size_t)su[i] * 128) + lane);
            v[i] = ldcg_f4(reinterpret_cast<const float4*>(
                       game_h + (size_t)sg[i] * 128) + lane);
        }

        float r[EDGES_PER_WARP];
        #pragma unroll
        for (int i = 0; i < EDGES_PER_WARP; i++) {
            float acc = u[i].x * v[i].x;
            acc = fmaf(u[i].y, v[i].y, acc);
            acc = fmaf(u[i].z, v[i].z, acc);
            acc = fmaf(u[i].w, v[i].w, acc);
            r[i] = warp_reduce(acc);
        }

        // r[i] is valid in every lane; lane i writes edge e0+i.
        if (lane < EDGES_PER_WARP) {
            float val = r[0];
            if (lane == 1) val = r[1];
            if (lane == 2) val = r[2];
            if (lane == 3) val = r[3];
            out[e0 + lane] = val;
        }
    } else {
        // ---- tail: per-edge ----
        for (int e = e0; e < num_edges; e++) {
            int su = min(max(src_idx[e], 0), n_users - 1);
            int sg = min(max(dst_idx[e], 0), n_games - 1);
            float4 u = ldcg_f4(reinterpret_cast<const float4*>(
                           user_h + (size_t)su * 128) + lane);
            float4 v = ldcg_f4(reinterpret_cast<const float4*>(
                           game_h + (size_t)sg * 128) + lane);
            float acc = u.x * v.x;
            acc = fmaf(u.y, v.y, acc);
            acc = fmaf(u.z, v.z, acc);
            acc = fmaf(u.w, v.w, acc);
            acc = warp_reduce(acc);
            if (lane == 0) out[e] = acc;
        }
    }
}

extern "C" void kernel_launch(void* const* d_in, const int* in_sizes, int n_in,
                              void* d_out, int out_size)
{
    const float* user_h  = (const float*)d_in[0];
    const float* game_h  = (const float*)d_in[1];
    const int*   src_idx = (const int*)d_in[2];
    const int*   dst_idx = (const int*)d_in[3];
    float*       out     = (float*)d_out;

    const int num_edges = in_sizes[2];
    const int n_users   = in_sizes[0] / 128;
    const int n_games   = in_sizes[1] / 128;

    const int edges_per_block = WARPS_PER_BLOCK * EDGES_PER_WARP;
    const int grid = (num_edges + edges_per_block - 1) / edges_per_block;
    edge_dot_kernel<<<grid, THREADS_PER_BLOCK>>>(
        user_h, game_h, src_idx, dst_idx, out, num_edges, n_users, n_games);
}

// round 4
// speedup vs baseline: 2.0800x; 1.0638x over previous
#include <cuda_runtime.h>
#include <cstdint>

// Edge-wise u·v scoring (DGL fn.u_dot_v)
//   d_in[0] user_h : [100000, 128] float32
//   d_in[1] game_h : [ 50000, 128] float32
//   d_in[2] src_idx: [E] int32
//   d_in[3] dst_idx: [E] int32
//   d_out   score  : [E, 1] float32
//
// R4: L1tex-wavefront optimization. R3 was L1-bound (84.4%) at ~2x the pure
// data floor, consistent with ~2 cyc/wavefront replay cost WITHIN one LDG.128.
// Split each 512B row read into two LDG.64s so wavefronts come from distinct
// instructions and pipeline at ~1 cyc/wf. Also: 14-shuffle reduction for the
// 4-edge batch instead of 20.

#define WARPS_PER_BLOCK 8
#define THREADS_PER_BLOCK (WARPS_PER_BLOCK * 32)
#define EDGES_PER_WARP 4

__global__ void __launch_bounds__(THREADS_PER_BLOCK)
edge_dot_kernel(const float* __restrict__ user_h,
                const float* __restrict__ game_h,
                const int* __restrict__ src_idx,
                const int* __restrict__ dst_idx,
                float* __restrict__ out,
                int num_edges,
                int n_users,
                int n_games)
{
    const int warp_in_block = threadIdx.x >> 5;
    const int lane          = threadIdx.x & 31;
    const int warp_id = blockIdx.x * WARPS_PER_BLOCK + warp_in_block;
    const int e0 = warp_id * EDGES_PER_WARP;
    if (e0 >= num_edges) return;

    if (e0 + EDGES_PER_WARP <= num_edges) {
        // ---- fast path: 4 edges ----
        int su[EDGES_PER_WARP], sg[EDGES_PER_WARP];
        #pragma unroll
        for (int i = 0; i < EDGES_PER_WARP; i++) {
            su[i] = min(max(src_idx[e0 + i], 0), n_users - 1);
            sg[i] = min(max(dst_idx[e0 + i], 0), n_games - 1);
        }

        // 16 independent LDG.64s issued before any consumption.
        // Row = 128 floats = 64 float2; lane covers float2 {lane, lane+32}.
        float2 u0[EDGES_PER_WARP], u1[EDGES_PER_WARP];
        float2 v0[EDGES_PER_WARP], v1[EDGES_PER_WARP];
        #pragma unroll
        for (int i = 0; i < EDGES_PER_WARP; i++) {
            const float2* up = reinterpret_cast<const float2*>(
                                   user_h + (size_t)su[i] * 128);
            const float2* gp = reinterpret_cast<const float2*>(
                                   game_h + (size_t)sg[i] * 128);
            u0[i] = __ldcg(up + lane);
            u1[i] = __ldcg(up + lane + 32);
            v0[i] = __ldcg(gp + lane);
            v1[i] = __ldcg(gp + lane + 32);
        }

        float acc[EDGES_PER_WARP];
        #pragma unroll
        for (int i = 0; i < EDGES_PER_WARP; i++) {
            float a = u0[i].x * v0[i].x;
            a = fmaf(u0[i].y, v0[i].y, a);
            a = fmaf(u1[i].x, v1[i].x, a);
            a = fmaf(u1[i].y, v1[i].y, a);
            acc[i] = a;
        }

        // Split butterfly: stages 16,8,4 per edge -> acc[i] holds, at lane l,
        // the partial sum over the 8 lanes sharing (l & 3).
        #pragma unroll
        for (int i = 0; i < EDGES_PER_WARP; i++) {
            acc[i] += __shfl_xor_sync(0xFFFFFFFFu, acc[i], 16);
            acc[i] += __shfl_xor_sync(0xFFFFFFFFu, acc[i], 8);
            acc[i] += __shfl_xor_sync(0xFFFFFFFFu, acc[i], 4);
        }

        // Each 4-lane group picks one edge's partial, then 2 shared stages
        // sum over (l & 3): lane l ends with the total for edge (l>>2)&3.
        const int j = (lane >> 2) & 3;
        float val = acc[0];
        if (j == 1) val = acc[1];
        if (j == 2) val = acc[2];
        if (j == 3) val = acc[3];
        val += __shfl_xor_sync(0xFFFFFFFFu, val, 2);
        val += __shfl_xor_sync(0xFFFFFFFFu, val, 1);

        // lanes 0,4,8,12 write edges e0+0..3 (one coalesced wavefront).
        if ((lane & 3) == 0 && lane < 16)
            out[e0 + j] = val;
    } else {
        // ---- tail: per-edge ----
        for (int e = e0; e < num_edges; e++) {
            int su = min(max(src_idx[e], 0), n_users - 1);
            int sg = min(max(dst_idx[e], 0), n_games - 1);
            const float2* up = reinterpret_cast<const float2*>(
                                   user_h + (size_t)su * 128);
            const float2* gp = reinterpret_cast<const float2*>(
                                   game_h + (size_t)sg * 128);
            float2 a0 = __ldcg(up + lane);
            float2 a1 = __ldcg(up + lane + 32);
            float2 b0 = __ldcg(gp + lane);
            float2 b1 = __ldcg(gp + lane + 32);
            float a = a0.x * b0.x;
            a = fmaf(a0.y, b0.y, a);
            a = fmaf(a1.x, b1.x, a);
            a = fmaf(a1.y, b1.y, a);
            #pragma unroll
            for (int ofs = 16; ofs > 0; ofs >>= 1)
                a += __shfl_xor_sync(0xFFFFFFFFu, a, ofs);
            if (lane == 0) out[e] = a;
        }
    }
}

extern "C" void kernel_launch(void* const* d_in, const int* in_sizes, int n_in,
                              void* d_out, int out_size)
{
    const float* user_h  = (const float*)d_in[0];
    const float* game_h  = (const float*)d_in[1];
    const int*   src_idx = (const int*)d_in[2];
    const int*   dst_idx = (const int*)d_in[3];
    float*       out     = (float*)d_out;

    const int num_edges = in_sizes[2];
    const int n_users   = in_sizes[0] / 128;
    const int n_games   = in_sizes[1] / 128;

    const int edges_per_block = WARPS_PER_BLOCK * EDGES_PER_WARP;
    const int grid = (num_edges + edges_per_block - 1) / edges_per_block;
    edge_dot_kernel<<<grid, THREADS_PER_BLOCK>>>(
        user_h, game_h, src_idx, dst_idx, out, num_edges, n_users, n_games);
}